// round 2
// baseline (speedup 1.0000x reference)
#include <cuda_runtime.h>

#define C 128
#define G_SEG 1024
#define MAX_N 1000000

// Scratch (no allocations allowed in kernel_launch)
static __device__ float g_logits[MAX_N];     // pass1: logits; pass2: exp(logit-max)
static __device__ unsigned int g_maxbits;    // encoded global max
static __device__ float g_sum;               // global softmax denominator

// Monotonic float<->uint encoding for atomicMax on floats (any sign)
__device__ __forceinline__ unsigned int enc_f(float x) {
    unsigned int b = __float_as_uint(x);
    return (b & 0x80000000u) ? ~b : (b | 0x80000000u);
}
__device__ __forceinline__ float dec_f(unsigned int k) {
    return (k & 0x80000000u) ? __uint_as_float(k ^ 0x80000000u)
                             : __uint_as_float(~k);
}

// k0: zero pooled output region + reset scalars (d_out is poisoned to 0xAA)
__global__ void k_zero(float* __restrict__ pooled) {
    int i = blockIdx.x * blockDim.x + threadIdx.x;
    if (i < G_SEG * C) pooled[i] = 0.0f;
    if (i == 0) { g_maxbits = 0u; g_sum = 0.0f; }
}

// k1: logits[i] = x[i,:].W + b  (warp per row, float4 per lane), global max
__global__ void k_logits(const float* __restrict__ x,
                         const float* __restrict__ W,
                         const float* __restrict__ b, int N) {
    __shared__ float s_w[C];
    for (int i = threadIdx.x; i < C; i += blockDim.x) s_w[i] = W[i];
    __syncthreads();

    const int lane   = threadIdx.x & 31;
    const int warp   = (blockIdx.x * blockDim.x + threadIdx.x) >> 5;
    const int nwarps = (gridDim.x * blockDim.x) >> 5;
    const float4 wv  = reinterpret_cast<const float4*>(s_w)[lane];
    const float  bb  = b[0];

    float lmax = -3.4e38f;
    for (int i = warp; i < N; i += nwarps) {
        float4 xv = reinterpret_cast<const float4*>(x + (size_t)i * C)[lane];
        float d = xv.x * wv.x + xv.y * wv.y + xv.z * wv.z + xv.w * wv.w;
        #pragma unroll
        for (int o = 16; o; o >>= 1) d += __shfl_xor_sync(0xffffffffu, d, o);
        if (lane == 0) {
            float l = d + bb;
            g_logits[i] = l;
            lmax = fmaxf(lmax, l);
        }
    }

    __shared__ float s_max[32];
    if (lane == 0) s_max[threadIdx.x >> 5] = lmax;
    __syncthreads();
    if (threadIdx.x == 0) {
        float m = -3.4e38f;
        int nw = blockDim.x >> 5;
        for (int w = 0; w < nw; w++) m = fmaxf(m, s_max[w]);
        atomicMax(&g_maxbits, enc_f(m));
    }
}

// k2: e_i = exp(logit_i - gmax), overwrite g_logits, accumulate global sum
__global__ void k_expsum(int N) {
    const float gmax = dec_f(g_maxbits);
    float s = 0.0f;
    int stride = gridDim.x * blockDim.x;
    for (int i = blockIdx.x * blockDim.x + threadIdx.x; i < N; i += stride) {
        float e = expf(g_logits[i] - gmax);
        g_logits[i] = e;
        s += e;
    }
    // block reduce
    __shared__ float s_red[32];
    #pragma unroll
    for (int o = 16; o; o >>= 1) s += __shfl_xor_sync(0xffffffffu, s, o);
    if ((threadIdx.x & 31) == 0) s_red[threadIdx.x >> 5] = s;
    __syncthreads();
    if (threadIdx.x < 32) {
        float v = (threadIdx.x < (blockDim.x >> 5)) ? s_red[threadIdx.x] : 0.0f;
        #pragma unroll
        for (int o = 16; o; o >>= 1) v += __shfl_xor_sync(0xffffffffu, v, o);
        if (threadIdx.x == 0) atomicAdd(&g_sum, v);
    }
}

// k3: alpha_i = e_i / sum  -> written into d_out's alpha region
__global__ void k_alpha(float* __restrict__ alpha, int N) {
    const float inv = 1.0f / g_sum;
    int stride = gridDim.x * blockDim.x;
    for (int i = blockIdx.x * blockDim.x + threadIdx.x; i < N; i += stride)
        alpha[i] = g_logits[i] * inv;
}

// k4: pooled[g, c] += alpha_i * x[i, c] over contiguous sorted segments.
// One block = 128 channel threads x ROWS_PER_BLOCK rows; register accumulate,
// atomicAdd only at segment boundaries / chunk edges.
// batch is int32 (JAX silently downcasts int64 without x64 mode).
#define ROWS_PER_BLOCK 256
__global__ void __launch_bounds__(128) k_pool(const float* __restrict__ x,
                                              const int* __restrict__ batch,
                                              const float* __restrict__ alpha,
                                              float* __restrict__ pooled, int N) {
    int start = blockIdx.x * ROWS_PER_BLOCK;
    if (start >= N) return;
    int end = min(N, start + ROWS_PER_BLOCK);
    const int c = threadIdx.x;

    int cur = batch[start];
    float acc = 0.0f;

    #pragma unroll 4
    for (int i = start; i < end; i++) {
        int g = batch[i];
        float a  = __ldg(alpha + i);
        float xv = __ldg(x + (size_t)i * C + c);
        if (g != cur) {
            int gc = min(max(cur, 0), G_SEG - 1);
            atomicAdd(&pooled[gc * C + c], acc);
            acc = 0.0f;
            cur = g;
        }
        acc = fmaf(a, xv, acc);
    }
    int gc = min(max(cur, 0), G_SEG - 1);
    atomicAdd(&pooled[gc * C + c], acc);
}

extern "C" void kernel_launch(void* const* d_in, const int* in_sizes, int n_in,
                              void* d_out, int out_size) {
    // Defensive input mapping by element counts:
    //   x: N*C (largest), W: C, b: 1, batch: N
    const float* x = nullptr;
    const float* W = nullptr;
    const float* b = nullptr;
    const int*   batch = nullptr;
    int N = 0;

    // First find x (largest input), derive N
    {
        int xi = 0;
        for (int i = 1; i < n_in; i++) if (in_sizes[i] > in_sizes[xi]) xi = i;
        x = (const float*)d_in[xi];
        N = in_sizes[xi] / C;
        for (int i = 0; i < n_in; i++) {
            if (i == xi) continue;
            if (in_sizes[i] == C)      W = (const float*)d_in[i];
            else if (in_sizes[i] == 1) b = (const float*)d_in[i];
            else if (in_sizes[i] == N) batch = (const int*)d_in[i];
        }
    }

    float* pooled = (float*)d_out;             // [G_SEG, C]
    float* alpha  = (float*)d_out + G_SEG * C; // [N]

    // k0: init outputs + scalars
    k_zero<<<(G_SEG * C + 255) / 256, 256>>>(pooled);

    // k1: logits + global max  (reads x once: 512 MB)
    k_logits<<<1480, 256>>>(x, W, b, N);

    // k2: exp + global sum (4 MB logits array)
    k_expsum<<<1024, 256>>>(N);

    // k3: alpha written to d_out
    k_alpha<<<2048, 256>>>(alpha, N);

    // k4: segment-pooled weighted sum (reads x again: 512 MB)
    k_pool<<<(N + ROWS_PER_BLOCK - 1) / ROWS_PER_BLOCK, 128>>>(x, batch, alpha, pooled, N);
}